// round 8
// baseline (speedup 1.0000x reference)
#include <cuda_runtime.h>

#define FULLMASK 0xFFFFFFFFu

// One warp per 4096-element SEGMENT of a (b,c) row. Segments independent via
// a decayed warm-up halo (g^halo < 1e-10 => exact at fp32; clamps to row
// start / exact full-scan fallback if g ~ 1). Tile = 256 elements: lane owns
// 8 contiguous elements (two float4s).
//   per-lane 8-elem chain tail -> warp Kogge-Stone over lane tails (ratio
//   g^8) -> cross-tile carry with g^256 -> outputs reconstructed with the
//   exact serial recurrence seeded from the scan state.
// Prefetch depth 2: tiles t+1 and t+2 are register-resident, keeping 4
// LDG.128 in flight across the entire shuffle chain.
__global__ void __launch_bounds__(128, 9)
ema_scan_pf2_kernel(const float4* __restrict__ x4,
                    const float* __restrict__ w,
                    float4* __restrict__ out4,
                    int Cdim, int T, int nrows, int nseg)
{
    constexpr int SEG_TILES = 16;             // 16 * 256 = 4096 elems/segment
    const int warp = threadIdx.x >> 5;
    const int lane = threadIdx.x & 31;
    const int gw   = blockIdx.x * 4 + warp;   // global segment id
    const int row  = gw / nseg;
    const int seg  = gw - row * nseg;
    if (row >= nrows) return;

    const float g   = __ldg(&w[row % Cdim]);
    const float omg = 1.0f - g;

    const float g2   = g * g;
    const float g4   = g2 * g2;
    const float g8   = g4 * g4;               // lane-step ratio
    const float g16  = g8 * g8;
    const float g32  = g16 * g16;
    const float g64  = g32 * g32;
    const float g128 = g64 * g64;
    const float g256 = g128 * g128;           // tile-step ratio

    // g^(8*lane) by binary decomposition
    float pl = 1.0f;
    if (lane & 1)  pl *= g8;
    if (lane & 2)  pl *= g16;
    if (lane & 4)  pl *= g32;
    if (lane & 8)  pl *= g64;
    if (lane & 16) pl *= g128;

    // warm-up tiles: g^(256*wt) < 1e-10; exact fallback if g ~ 1
    int wt;
    if (g > 0.0f && g < 0.9999f)
        wt = (int)((-23.03f * (1.0f / 256.0f)) / __logf(g)) + 1;
    else
        wt = 0x3fffffff;
    const int seg_tile0 = seg * SEG_TILES;
    if (wt > seg_tile0) wt = seg_tile0;
    if (wt < 0) wt = 0;

    const float4* __restrict__ xin  = x4   + (size_t)row * (T >> 2);
    float4*       __restrict__ yout = out4 + (size_t)row * (T >> 2);

    const int tile_begin = seg_tile0 - wt;
    const int count      = wt + SEG_TILES;

    float C = 0.0f;

    int base = tile_begin * 64 + 2 * lane;

    // prime the 2-deep pipeline
    float4 a0 = __ldcs(xin + base);
    float4 a1 = __ldcs(xin + base + 1);
    float4 p0, p1;
    if (count > 1) { p0 = __ldcs(xin + base + 64); p1 = __ldcs(xin + base + 65); }
    else           { p0 = a0; p1 = a1; }

    #pragma unroll 1
    for (int t = 0; t < count; ++t) {
        // issue the t+2 loads first so 4 LDG are in flight during the chain
        float4 q0 = p0, q1 = p1;
        if (t + 2 < count) {
            q0 = __ldcs(xin + base + 128);
            q1 = __ldcs(xin + base + 129);
        }

        // per-lane chain tail over 8 contiguous elements
        float l = a0.x * omg;
        l = fmaf(g, l, a0.y * omg);
        l = fmaf(g, l, a0.z * omg);
        l = fmaf(g, l, a0.w * omg);
        l = fmaf(g, l, a1.x * omg);
        l = fmaf(g, l, a1.y * omg);
        l = fmaf(g, l, a1.z * omg);
        l = fmaf(g, l, a1.w * omg);

        // warp inclusive scan of lane tails, ratio g^8
        float v = l, tv;
        tv = __shfl_up_sync(FULLMASK, v, 1);  if (lane >= 1)  v = fmaf(g8,   tv, v);
        tv = __shfl_up_sync(FULLMASK, v, 2);  if (lane >= 2)  v = fmaf(g16,  tv, v);
        tv = __shfl_up_sync(FULLMASK, v, 4);  if (lane >= 4)  v = fmaf(g32,  tv, v);
        tv = __shfl_up_sync(FULLMASK, v, 8);  if (lane >= 8)  v = fmaf(g64,  tv, v);
        tv = __shfl_up_sync(FULLMASK, v, 16); if (lane >= 16) v = fmaf(g128, tv, v);

        // exclusive carry from earlier lanes
        float cL = __shfl_up_sync(FULLMASK, v, 1);
        if (lane == 0) cL = 0.0f;

        if (t >= wt) {
            // EMA state just before this lane's first element, then exact
            // serial reconstruction of the 8 outputs
            float y = fmaf(pl, C, cL);
            float4 o0, o1;
            y = fmaf(g, y, a0.x * omg);  o0.x = y;
            y = fmaf(g, y, a0.y * omg);  o0.y = y;
            y = fmaf(g, y, a0.z * omg);  o0.z = y;
            y = fmaf(g, y, a0.w * omg);  o0.w = y;
            y = fmaf(g, y, a1.x * omg);  o1.x = y;
            y = fmaf(g, y, a1.y * omg);  o1.y = y;
            y = fmaf(g, y, a1.z * omg);  o1.z = y;
            y = fmaf(g, y, a1.w * omg);  o1.w = y;
            __stcs(yout + base,     o0);
            __stcs(yout + base + 1, o1);
        }

        // cross-tile carry
        C = fmaf(g256, C, __shfl_sync(FULLMASK, v, 31));

        // rotate the pipeline
        a0 = p0; a1 = p1;
        p0 = q0; p1 = q1;
        base += 64;
    }
}

extern "C" void kernel_launch(void* const* d_in, const int* in_sizes, int n_in,
                              void* d_out, int out_size)
{
    const float4* x4 = (const float4*)d_in[0];
    const float*  w  = (const float*)d_in[1];
    float4* out4 = (float4*)d_out;

    const int Cdim  = in_sizes[1];          // 512
    const int T     = 16384;                // fixed problem shape
    const int nrows = in_sizes[0] / T;      // B*C = 4096
    const int nseg  = T / 4096;             // 4 segments per row

    const int total_warps     = nrows * nseg;   // 16384
    const int warps_per_block = 4;
    dim3 block(32 * warps_per_block);           // 128 threads
    dim3 grid((total_warps + warps_per_block - 1) / warps_per_block);
    ema_scan_pf2_kernel<<<grid, block>>>(x4, w, out4, Cdim, T, nrows, nseg);
}